// round 10
// baseline (speedup 1.0000x reference)
#include <cuda_runtime.h>

// Problem constants
constexpr int Tn = 1000, Dd = 64, Nn = 128, Bb = 1000;
constexpr int GROUPS = 4;                 // independent row-sims per CTA
constexpr int TPB = GROUPS * Nn;          // 512 threads
constexpr int GRID = Bb / GROUPS;         // 250 CTAs -> 1000 groups = 1000 rows

// KEY INSIGHT 1: reference broadcasts x_t across all B rows from identical
// zero state => all B rows produce identical outputs; every group just
// re-runs the (cheap) sim for its own row and writes it.
// KEY INSIGHT 2 (R10): all prior designs were latency-bound (~1200 cyc/step
// serial path, nothing saturated) with only ~2 independent chains per SMSP.
// Pack 4 independent 128-thread sim groups per CTA (named barriers, one
// shared 64KB W copy), 2 CTAs/SM => 8 independent chains per SMSP.

__device__ float g_inp_cur[Tn * Nn];  // (T, N) input currents

// ---------------------------------------------------------------------------
// Kernel A: input currents (1000x64 @ 64x128). ~5us.
// ---------------------------------------------------------------------------
__global__ void inp_cur_kernel(const float* __restrict__ sig,
                               const float* __restrict__ w_in) {
    int t = blockIdx.x, n = threadIdx.x;
    float acc = 0.f;
#pragma unroll
    for (int d = 0; d < Dd; ++d) acc += sig[t * Dd + d] * w_in[d * Nn + n];
    g_inp_cur[t * Nn + n] = acc;
}

// ---------------------------------------------------------------------------
// Kernel B: 4 independent row-sims per CTA. Thread = neuron n of group g.
//   Per step (per group): scalar update -> ballot -> STS(1 word/warp) ->
//   bar.sync(g+1, 128) -> LDS.128 mask words -> serial-ffs sparse walk
//   (spike counts are low) -> 2 coalesced history stores.
//   Masks double-buffered by t&1; ONE named barrier per step per group.
// ---------------------------------------------------------------------------
__global__ __launch_bounds__(TPB, 2)
void sim_kernel(const float* __restrict__ Wrec, float* __restrict__ out) {
    extern __shared__ float sW[];                       // 128*128 = 64KB
    __shared__ __align__(16) unsigned smask[2][GROUPS][4];  // [buf][group][warp]

    const int tid = threadIdx.x;
    const int g = tid >> 7;          // group 0..3
    const int n = tid & 127;         // neuron 0..127
    const int gw = (tid >> 5) & 3;   // warp within group
    const int lane = tid & 31;
    const int row = blockIdx.x * GROUPS + g;   // 0..999 exact

    // Cooperative load of W (shared by all 4 groups)
    {
        float4* dst = reinterpret_cast<float4*>(sW);
        const float4* src = reinterpret_cast<const float4*>(Wrec);
        for (int i = tid; i < (Nn * Nn) / 4; i += TPB) dst[i] = src[i];
    }
    __syncthreads();

    float* __restrict__ o_spk = out + (size_t)row * Tn * Nn + n;
    float* __restrict__ o_mem = o_spk + (size_t)Bb * Tn * Nn;

    float syn = 0.f, mem = 0.f, refr = 0.f, rec = 0.f, trc = 0.f;

    const float* __restrict__ xin = g_inp_cur;
    const float* __restrict__ wp = sW + n;    // W[k][n] = wp[k*128]

    float x = xin[n];

    for (int t = 0; t < Tn; ++t) {
        const int tnn = (t + 1 < Tn) ? (t + 1) : t;
        const float xn = __ldg(&xin[tnn * Nn + n]);

        // ---- neuron update (order matches reference) ----
        syn = syn * 0.8f + (x + rec);
        mem = mem * 0.9f + syn * 0.1f;
        mem = (refr > 0.f) ? 0.f : mem;
        refr = fmaxf(refr - 1.f, 0.f);
        const bool k = mem > 1.0f;
        const float s = k ? 1.f : 0.f;
        mem = k ? 0.f : mem;
        refr += s * 2.f;
        trc = trc * 0.95f + s;

        // ---- publish this warp's spike word; group-local barrier ----
        const unsigned mw = __ballot_sync(0xFFFFFFFFu, k);
        const int buf = t & 1;
        if (lane == 0) smask[buf][g][gw] = mw;

        // ---- history stores (128B coalesced, fire-and-forget) ----
        o_spk[t * Nn] = s;
        o_mem[t * Nn] = mem;

        asm volatile("bar.sync %0, 128;" :: "r"(g + 1) : "memory");
        const uint4 mm = *reinterpret_cast<const uint4*>(&smask[buf][g][0]);

        // ---- sparse accumulate: rec = 0.95*rec + sum_{spiking src} W[src][n]
        float acc = 0.f;
#pragma unroll
        for (int j = 0; j < 4; ++j) {
            unsigned m = (j == 0) ? mm.x : (j == 1) ? mm.y
                        : (j == 2) ? mm.z : mm.w;
            while (m) {
                const int l = __ffs(m) - 1; m &= m - 1;
                acc += wp[(j * 32 + l) * Nn];
            }
        }
        rec = rec * 0.95f + acc;

        x = xn;
    }

    // ---- final trace for this group's row ----
    out[(size_t)2 * Bb * Tn * Nn + (size_t)row * Nn + n] = trc;
}

// ---------------------------------------------------------------------------
// Harness entry
// ---------------------------------------------------------------------------
extern "C" void kernel_launch(void* const* d_in, const int* in_sizes, int n_in,
                              void* d_out, int out_size) {
    const float* sig   = (const float*)d_in[0];  // (1000, 64)
    const float* w_in  = (const float*)d_in[1];  // (64, 128)
    const float* w_rec = (const float*)d_in[2];  // (128, 128)
    float* out = (float*)d_out;
    (void)in_sizes; (void)n_in; (void)out_size;

    const int smem = Nn * Nn * (int)sizeof(float);   // 65536 B
    cudaFuncSetAttribute(sim_kernel,
                         cudaFuncAttributeMaxDynamicSharedMemorySize, smem);

    inp_cur_kernel<<<Tn, Nn>>>(sig, w_in);
    sim_kernel<<<GRID, TPB, smem>>>(w_rec, out);
}